// round 12
// baseline (speedup 1.0000x reference)
#include <cuda_runtime.h>
#include <cuda_bf16.h>
#include <stdint.h>

#define N_NODES  100000
#define N_EDGES  1600000
#define D        128
#define N_LAYERS 7
#define N_GRAPHS 64
#define N_CLASSES 10
#define SNN_IN   512
#define SNN_H    1024

typedef __nv_bfloat16 bf16;

// ---------------- device scratch (no allocations allowed) ----------------
__device__ __align__(16) bf16 g_xH [(size_t)N_NODES * D];
__device__ __align__(16) bf16 g_xL [(size_t)N_NODES * D];
__device__ __align__(16) bf16 g_hAH[(size_t)N_NODES * D];
__device__ __align__(16) bf16 g_hAL[(size_t)N_NODES * D];
__device__ __align__(16) bf16 g_hBH[(size_t)N_NODES * D];
__device__ __align__(16) bf16 g_hBL[(size_t)N_NODES * D];

// pre-split weights, [layer][rel/root][n=128][k=128]
__device__ __align__(16) bf16 g_wH[N_LAYERS * 2 * D * D];
__device__ __align__(16) bf16 g_wL[N_LAYERS * 2 * D * D];

__device__ int   g_cnt   [N_NODES];
__device__ int   g_rowptr[N_NODES + 1];
__device__ int   g_cursor[N_NODES];
__device__ int   g_col   [N_EDGES];

__device__ float g_pool[N_GRAPHS * D];
__device__ float g_cnts[N_GRAPHS];
__device__ float g_snnh[N_GRAPHS * SNN_H];

__device__ int   g_is64;

// ---------------- small helpers ----------------
__device__ __forceinline__ uint32_t bf2pack(float a, float b) {
    __nv_bfloat162 t = __float22bfloat162_rn(make_float2(a, b));
    return *(uint32_t*)&t;
}
__device__ __forceinline__ int idx_at(const void* __restrict__ p, long long i, int is64) {
    long long v = is64 ? ((const long long*)p)[i] : (long long)((const int*)p)[i];
    return (int)v;
}
__device__ __forceinline__ int clampi(int v, int lo, int hi) {
    return v < lo ? lo : (v > hi ? hi : v);
}
__device__ __forceinline__ uint32_t smem_u32(const void* p) {
    uint32_t a;
    asm("{ .reg .u64 t; cvta.to.shared.u64 t, %1; cvt.u32.u64 %0, t; }" : "=r"(a) : "l"(p));
    return a;
}
__device__ __forceinline__ void cp16(uint32_t dst, const void* src) {
    asm volatile("cp.async.cg.shared.global [%0], [%1], 16;" :: "r"(dst), "l"(src));
}
#define CP_COMMIT asm volatile("cp.async.commit_group;" ::: "memory")

// ---------------- dtype detection ----------------
__global__ void detect_kernel(const int* __restrict__ ei32) {
    if (threadIdx.x == 0 && blockIdx.x == 0) {
        int orr = 0;
        #pragma unroll 8
        for (int i = 1; i < 256; i += 2) orr |= ei32[i];
        g_is64 = (orr == 0) ? 1 : 0;
    }
}

// ---------------- x -> hi/lo bf16 ----------------
__global__ void xconv_kernel(const float* __restrict__ x) {
    size_t i = (size_t)blockIdx.x * blockDim.x + threadIdx.x;
    size_t n4 = (size_t)N_NODES * D / 4;
    if (i >= n4) return;
    float4 v = ((const float4*)x)[i];
    uint32_t h01 = bf2pack(v.x, v.y), h23 = bf2pack(v.z, v.w);
    float r0 = v.x - __bfloat162float(((__nv_bfloat162*)&h01)->x);
    float r1 = v.y - __bfloat162float(((__nv_bfloat162*)&h01)->y);
    float r2 = v.z - __bfloat162float(((__nv_bfloat162*)&h23)->x);
    float r3 = v.w - __bfloat162float(((__nv_bfloat162*)&h23)->y);
    ((uint2*)g_xH)[i] = make_uint2(h01, h23);
    ((uint2*)g_xL)[i] = make_uint2(bf2pack(r0, r1), bf2pack(r2, r3));
}

// ---------------- weight pre-split: [l][s][n][k] ----------------
__global__ void wprep_kernel(const float* __restrict__ cwrel,
                             const float* __restrict__ cwroot) {
    int b = blockIdx.x;                 // l*256 + s*128 + k
    int l = b >> 8, s = (b >> 7) & 1, k = b & 127;
    int n = threadIdx.x;
    const float* w = (s ? cwroot : cwrel) + (size_t)l * D * D;
    float v = w[k * D + n];
    bf16 h = __float2bfloat16(v);
    float r = v - __bfloat162float(h);
    size_t o = ((size_t)(l * 2 + s) * D + n) * D + k;
    g_wH[o] = h;
    g_wL[o] = __float2bfloat16(r);
}

// ---------------- CSR build ----------------
__global__ void zero_kernel() {
    int i = blockIdx.x * blockDim.x + threadIdx.x;
    if (i < N_NODES) g_cnt[i] = 0;
    if (i < N_GRAPHS * D) g_pool[i] = 0.f;
    if (i < N_GRAPHS) g_cnts[i] = 0.f;
}

__global__ void hist_kernel(const void* __restrict__ ei) {
    int e = blockIdx.x * blockDim.x + threadIdx.x;
    if (e >= N_EDGES) return;
    int dst = clampi(idx_at(ei, (long long)N_EDGES + e, g_is64), 0, N_NODES - 1);
    atomicAdd(&g_cnt[dst], 1);
}

// single-block scan, 4 elems/thread, warp-shuffle based
__global__ void scan_kernel() {
    __shared__ int wsum[32];
    __shared__ int s_carry;
    int tid = threadIdx.x, lane = tid & 31, wid = tid >> 5;
    if (tid == 0) { s_carry = 0; g_rowptr[0] = 0; }
    __syncthreads();
    for (int base = 0; base < N_NODES; base += 4096) {
        int i0 = base + tid * 4;
        int v0 = 0, v1 = 0, v2 = 0, v3 = 0;
        if (i0 + 3 < N_NODES) {
            int4 v = *(const int4*)&g_cnt[i0];
            v0 = v.x; v1 = v.y; v2 = v.z; v3 = v.w;
        } else if (i0 < N_NODES) {
            v0 = g_cnt[i0];
            if (i0 + 1 < N_NODES) v1 = g_cnt[i0 + 1];
            if (i0 + 2 < N_NODES) v2 = g_cnt[i0 + 2];
        }
        int s0 = v0, s1 = s0 + v1, s2 = s1 + v2, s3 = s2 + v3;
        int t = s3;
        #pragma unroll
        for (int off = 1; off < 32; off <<= 1) {
            int u = __shfl_up_sync(0xFFFFFFFFu, t, off);
            if (lane >= off) t += u;
        }
        if (lane == 31) wsum[wid] = t;
        __syncthreads();
        if (wid == 0) {
            int w = wsum[lane];
            #pragma unroll
            for (int off = 1; off < 32; off <<= 1) {
                int u = __shfl_up_sync(0xFFFFFFFFu, w, off);
                if (lane >= off) w += u;
            }
            wsum[lane] = w;
        }
        __syncthreads();
        int warpoff = (wid > 0) ? wsum[wid - 1] : 0;
        int throff = s_carry + warpoff + (t - s3);
        if (i0 < N_NODES)     { g_cursor[i0]     = throff;      g_rowptr[i0 + 1] = throff + s0; }
        if (i0 + 1 < N_NODES) { g_cursor[i0 + 1] = throff + s0; g_rowptr[i0 + 2] = throff + s1; }
        if (i0 + 2 < N_NODES) { g_cursor[i0 + 2] = throff + s1; g_rowptr[i0 + 3] = throff + s2; }
        if (i0 + 3 < N_NODES) { g_cursor[i0 + 3] = throff + s2; g_rowptr[i0 + 4] = throff + s3; }
        int tot = wsum[31];
        __syncthreads();
        if (tid == 0) s_carry += tot;
        __syncthreads();
    }
}

__global__ void scatter_kernel(const void* __restrict__ ei) {
    int e = blockIdx.x * blockDim.x + threadIdx.x;
    if (e >= N_EDGES) return;
    int is64 = g_is64;
    int src = clampi(idx_at(ei, e, is64),                      0, N_NODES - 1);
    int dst = clampi(idx_at(ei, (long long)N_EDGES + e, is64), 0, N_NODES - 1);
    int pos = atomicAdd(&g_cursor[dst], 1);
    if (pos >= 0 && pos < N_EDGES) g_col[pos] = src;
}

// ============ fused aggregate + mma.sync bf16x3 GraphConv ============
// Phase 1: CTA gathers neighbor sums for its 128 rows into smem (hi/lo).
// Phase 2: K=256 in 8 chunks of 32; chunks 0-3 A=smem agg, 4-7 A=cur
// (staged into dead agg slots); B double-buffered via cp.async.

#define KC      32
#define SPITCH  80                 // B stage row pitch (conflict-free)
#define AGPITCH 272                // agg region row pitch (conflict-free)
#define AG_H    0
#define AG_L    34816
#define B_BASE  69632
#define B_STAGE 20480              // BH + BL
#define B_LOFF  10240
#define GT_SMEM_BYTES 110592       // 108 KB -> 2 CTAs/SM

__device__ __forceinline__ void mma16816(float* c,
    uint32_t a0, uint32_t a1, uint32_t a2, uint32_t a3,
    uint32_t b0, uint32_t b1)
{
    asm volatile(
        "mma.sync.aligned.m16n8k16.row.col.f32.bf16.bf16.f32 "
        "{%0,%1,%2,%3}, {%4,%5,%6,%7}, {%8,%9}, {%0,%1,%2,%3};"
        : "+f"(c[0]), "+f"(c[1]), "+f"(c[2]), "+f"(c[3])
        : "r"(a0), "r"(a1), "r"(a2), "r"(a3), "r"(b0), "r"(b1));
}

__global__ __launch_bounds__(256, 2) void gemm_fused(int sel, int layer,
                                                     const float* __restrict__ brel)
{
    extern __shared__ char sm[];
    uint32_t sb = smem_u32(sm);

    const bf16* __restrict__ curH = (sel == 2) ? g_xH : (sel == 1 ? g_hAH : g_hBH);
    const bf16* __restrict__ curL = (sel == 2) ? g_xL : (sel == 1 ? g_hAL : g_hBL);
    bf16* __restrict__ outH = (sel == 1) ? g_hBH : g_hAH;
    bf16* __restrict__ outL = (sel == 1) ? g_hBL : g_hAL;
    const bf16* __restrict__ wHb = g_wH + (size_t)layer * 2 * D * D;
    const bf16* __restrict__ wLb = g_wL + (size_t)layer * 2 * D * D;

    int tid  = threadIdx.x;
    int lane = tid & 31, wid = tid >> 5;
    int wm = wid & 3, wn = wid >> 2;           // warp grid 4(M) x 2(N)
    int l4 = lane >> 2, l2 = (lane & 3) * 2;
    int m0 = blockIdx.x * 128;

    // ---- load weight chunk c into B stage s ----
    auto load_B = [&](int c, int s) {
        const bf16* wHc = wHb + (c >= 4 ? D * D : 0) + (c & 3) * KC;
        const bf16* wLc = wLb + (c >= 4 ? D * D : 0) + (c & 3) * KC;
        #pragma unroll
        for (int i = 0; i < 4; i++) {
            int cid = (i & 1) * 256 + tid;           // 0..511
            int row = cid >> 2, ch = cid & 3;
            uint32_t dst = sb + B_BASE + s * B_STAGE + (i >> 1) * B_LOFF
                         + row * SPITCH + ch * 16;
            const bf16* srcb = (i >> 1) ? wLc : wHc;
            cp16(dst, srcb + (size_t)row * D + ch * 8);
        }
    };
    // ---- stage cur chunk c (4..7) into agg slot (c&3) ----
    auto load_cur = [&](int c) {
        #pragma unroll
        for (int i = 0; i < 4; i++) {
            int cid = (i & 1) * 256 + tid;
            int row = cid >> 2, ch = cid & 3;
            int m = m0 + row; if (m >= N_NODES) m = 0;
            uint32_t dst = sb + ((i >> 1) ? AG_L : AG_H) + row * AGPITCH
                         + (c & 3) * 64 + ch * 16;
            const bf16* srcb = (i >> 1) ? curL : curH;
            cp16(dst, srcb + (size_t)m * D + (c & 3) * KC + ch * 8);
        }
    };

    load_B(0, 0);
    CP_COMMIT;

    // ---- phase 1: gather-aggregate 16 rows per warp into smem agg ----
    #pragma unroll 1
    for (int r8 = 0; r8 < 16; r8++) {
        int row = wid * 16 + r8;
        int node = m0 + row;
        float4 acc = make_float4(0.f, 0.f, 0.f, 0.f);
        if (node < N_NODES) {
            int s0 = g_rowptr[node], e0 = g_rowptr[node + 1];
            for (int i = s0; i < e0; i++) {
                int src = g_col[i];
                size_t o = (size_t)src * D + lane * 4;
                uint2 hv = *(const uint2*)(curH + o);
                uint2 lv = *(const uint2*)(curL + o);
                float2 a0 = __bfloat1622float2(*(__nv_bfloat162*)&hv.x);
                float2 a1 = __bfloat1622float2(*(__nv_bfloat162*)&hv.y);
                float2 b0 = __bfloat1622float2(*(__nv_bfloat162*)&lv.x);
                float2 b1 = __bfloat1622float2(*(__nv_bfloat162*)&lv.y);
                acc.x += a0.x + b0.x; acc.y += a0.y + b0.y;
                acc.z += a1.x + b1.x; acc.w += a1.y + b1.y;
            }
        }
        uint32_t h01 = bf2pack(acc.x, acc.y), h23 = bf2pack(acc.z, acc.w);
        float r0 = acc.x - __bfloat162float(((__nv_bfloat162*)&h01)->x);
        float r1 = acc.y - __bfloat162float(((__nv_bfloat162*)&h01)->y);
        float r2 = acc.z - __bfloat162float(((__nv_bfloat162*)&h23)->x);
        float r3 = acc.w - __bfloat162float(((__nv_bfloat162*)&h23)->y);
        *(uint2*)(sm + AG_H + row * AGPITCH + lane * 8) = make_uint2(h01, h23);
        *(uint2*)(sm + AG_L + row * AGPITCH + lane * 8) =
            make_uint2(bf2pack(r0, r1), bf2pack(r2, r3));
    }
    asm volatile("cp.async.wait_group 0;" ::: "memory");
    __syncthreads();

    float acc[2][8][4];
    #pragma unroll
    for (int a = 0; a < 2; a++)
        #pragma unroll
        for (int t = 0; t < 8; t++)
            #pragma unroll
            for (int j = 0; j < 4; j++) acc[a][t][j] = 0.f;

    // ---- phase 2: 8 K-chunks ----
    #pragma unroll 1
    for (int c = 0; c < 8; c++) {
        if (c < 7) {
            load_B(c + 1, (c + 1) & 1);
            if (c + 1 >= 4) load_cur(c + 1);
            CP_COMMIT;
        }
        char* pBhi = sm + B_BASE + (c & 1) * B_STAGE;
        char* pBlo = pBhi + B_LOFF;
        char* pAhi = sm + AG_H;
        char* pAlo = sm + AG_L;
        int acol = (c & 3) * 64;                  // byte offset of chunk cols

        #pragma unroll
        for (int ks = 0; ks < KC; ks += 16) {
            uint32_t ah[2][4], al[2][4];
            #pragma unroll
            for (int mt = 0; mt < 2; mt++) {
                int r0 = wm * 32 + mt * 16 + l4;
                int cby = acol + (ks + l2) * 2;
                ah[mt][0] = *(uint32_t*)(pAhi + r0 * AGPITCH + cby);
                ah[mt][1] = *(uint32_t*)(pAhi + (r0 + 8) * AGPITCH + cby);
                ah[mt][2] = *(uint32_t*)(pAhi + r0 * AGPITCH + cby + 16);
                ah[mt][3] = *(uint32_t*)(pAhi + (r0 + 8) * AGPITCH + cby + 16);
                al[mt][0] = *(uint32_t*)(pAlo + r0 * AGPITCH + cby);
                al[mt][1] = *(uint32_t*)(pAlo + (r0 + 8) * AGPITCH + cby);
                al[mt][2] = *(uint32_t*)(pAlo + r0 * AGPITCH + cby + 16);
                al[mt][3] = *(uint32_t*)(pAlo + (r0 + 8) * AGPITCH + cby + 16);
            }
            #pragma unroll
            for (int t = 0; t < 8; t++) {
                int n = wn * 64 + t * 8 + l4;
                uint32_t boff = (uint32_t)(n * SPITCH + (ks + l2) * 2);
                uint32_t bh0 = *(uint32_t*)(pBhi + boff);
                uint32_t bh1 = *(uint32_t*)(pBhi + boff + 16);
                uint32_t bl0 = *(uint32_t*)(pBlo + boff);
                uint32_t bl1 = *(uint32_t*)(pBlo + boff + 16);
                #pragma unroll
                for (int mt = 0; mt < 2; mt++) {
                    mma16816(acc[mt][t], ah[mt][0], ah[mt][1], ah[mt][2], ah[mt][3], bh0, bh1);
                    mma16816(acc[mt][t], ah[mt][0], ah[mt][1], ah[mt][2], ah[mt][3], bl0, bl1);
                    mma16816(acc[mt][t], al[mt][0], al[mt][1], al[mt][2], al[mt][3], bh0, bh1);
                }
            }
        }
        if (c < 7) asm volatile("cp.async.wait_group 0;" ::: "memory");
        __syncthreads();
    }

    // ---- epilogue: bias + relu -> hi/lo bf16 out ----
    #pragma unroll
    for (int mt = 0; mt < 2; mt++) {
        int row = m0 + wm * 32 + mt * 16 + l4;
        #pragma unroll
        for (int t = 0; t < 8; t++) {
            int col = wn * 64 + t * 8 + l2;
            float2 bb = *(const float2*)(brel + col);
            #pragma unroll
            for (int h = 0; h < 2; h++) {
                int r = row + h * 8;
                if (r < N_NODES) {
                    float ox = fmaxf(acc[mt][t][h * 2 + 0] + bb.x, 0.f);
                    float oy = fmaxf(acc[mt][t][h * 2 + 1] + bb.y, 0.f);
                    uint32_t hp = bf2pack(ox, oy);
                    float rx = ox - __bfloat162float(((__nv_bfloat162*)&hp)->x);
                    float ry = oy - __bfloat162float(((__nv_bfloat162*)&hp)->y);
                    size_t o = (size_t)r * D + col;
                    *(uint32_t*)(outH + o) = hp;
                    *(uint32_t*)(outL + o) = bf2pack(rx, ry);
                }
            }
        }
    }
}

// ---------------- pooling (reads final h = bufA hi/lo) ----------------
#define POOL_CHUNK 512
__global__ void pool_kernel(const void* __restrict__ batch) {
    int ch = threadIdx.x;                   // 128
    int start = blockIdx.x * POOL_CHUNK;
    if (start >= N_NODES) return;
    int end = min(start + POOL_CHUNK, N_NODES);
    int is64 = g_is64;
    int cur = clampi(idx_at(batch, start, is64), 0, N_GRAPHS - 1);
    float acc = 0.f;
    for (int i = start; i < end; i++) {
        int b = clampi(idx_at(batch, i, is64), 0, N_GRAPHS - 1);
        if (b != cur) {
            atomicAdd(&g_pool[cur * D + ch], acc);
            acc = 0.f; cur = b;
        }
        size_t o = (size_t)i * D + ch;
        acc += __bfloat162float(g_hAH[o]) + __bfloat162float(g_hAL[o]);
    }
    atomicAdd(&g_pool[cur * D + ch], acc);
}

__global__ void count_kernel(const void* __restrict__ batch) {
    int i = blockIdx.x * blockDim.x + threadIdx.x;
    if (i >= N_NODES) return;
    int b = clampi(idx_at(batch, i, g_is64), 0, N_GRAPHS - 1);
    atomicAdd(&g_cnts[b], 1.f);
}

// ---------------- SNN layer 1 ----------------
__global__ void snn1_kernel(const float* __restrict__ x, const float* __restrict__ w1,
                            const float* __restrict__ b1) {
    __shared__ float xs[SNN_IN];
    int g = blockIdx.x;
    for (int i = threadIdx.x; i < SNN_IN; i += 256) xs[i] = x[g * SNN_IN + i];
    __syncthreads();
    #pragma unroll
    for (int j = 0; j < 4; j++) {
        int n = threadIdx.x + j * 256;
        float acc = b1[n];
        for (int k = 0; k < SNN_IN; k++)
            acc = fmaf(xs[k], w1[(size_t)k * SNN_H + n], acc);
        g_snnh[g * SNN_H + n] = fmaxf(acc, 0.f);
    }
}

// ---------------- final head + fusion ----------------
__global__ void head_kernel(const float* __restrict__ w2, const float* __restrict__ b2,
                            const float* __restrict__ linw, const float* __restrict__ linb,
                            const float* __restrict__ fw, const float* __restrict__ fb,
                            float* __restrict__ out) {
    __shared__ float s_snn[N_GRAPHS * N_CLASSES];
    __shared__ float s_gnn[N_GRAPHS * N_CLASSES];
    int t = threadIdx.x;                // 640
    int g = t / N_CLASSES, c = t % N_CLASSES;

    float acc = b2[c];
    for (int k = 0; k < SNN_H; k++)
        acc = fmaf(g_snnh[g * SNN_H + k], w2[k * N_CLASSES + c], acc);
    s_snn[g * N_CLASSES + c] = 0.85f * acc;

    float cnt = fmaxf(g_cnts[g], 1.0f);
    float inv = 1.0f / cnt;
    float acc2 = linb[c];
    for (int k = 0; k < D; k++)
        acc2 = fmaf(g_pool[g * D + k] * inv, linw[k * N_CLASSES + c], acc2);
    s_gnn[g * N_CLASSES + c] = acc2;
    __syncthreads();

    float o = fb[c];
    #pragma unroll
    for (int j = 0; j < N_CLASSES; j++) {
        o = fmaf(s_snn[g * N_CLASSES + j], fw[j * N_CLASSES + c], o);
        o = fmaf(s_gnn[g * N_CLASSES + j], fw[(N_CLASSES + j) * N_CLASSES + c], o);
    }
    out[g * N_CLASSES + c] = o;
}

// ---------------- launch ----------------
extern "C" void kernel_launch(void* const* d_in, const int* in_sizes, int n_in,
                              void* d_out, int out_size) {
    const float* snn_x  = (const float*)d_in[0];
    const float* x      = (const float*)d_in[1];
    const void*  ei     = d_in[2];
    const void*  batch  = d_in[3];
    const float* snn_w1 = (const float*)d_in[4];
    const float* snn_b1 = (const float*)d_in[5];
    const float* snn_w2 = (const float*)d_in[6];
    const float* snn_b2 = (const float*)d_in[7];
    const float* cwrel  = (const float*)d_in[8];
    const float* cwroot = (const float*)d_in[9];
    const float* cbrel  = (const float*)d_in[10];
    const float* lin_w  = (const float*)d_in[11];
    const float* lin_b  = (const float*)d_in[12];
    const float* fuse_w = (const float*)d_in[13];
    const float* fuse_b = (const float*)d_in[14];
    float* out = (float*)d_out;

    cudaFuncSetAttribute(gemm_fused, cudaFuncAttributeMaxDynamicSharedMemorySize,
                         GT_SMEM_BYTES);

    // dtype detection + pre-splits + CSR build
    detect_kernel<<<1, 32>>>((const int*)ei);
    xconv_kernel<<<(N_NODES * D / 4 + 255) / 256, 256>>>(x);
    wprep_kernel<<<N_LAYERS * 256, 128>>>(cwrel, cwroot);
    zero_kernel<<<(N_NODES + 255) / 256, 256>>>();
    hist_kernel<<<(N_EDGES + 255) / 256, 256>>>(ei);
    scan_kernel<<<1, 1024>>>();
    scatter_kernel<<<(N_EDGES + 255) / 256, 256>>>(ei);

    // SNN branch (independent)
    snn1_kernel<<<N_GRAPHS, 256>>>(snn_x, snn_w1, snn_b1);

    // 7 fused GraphConv layers: x -> A -> B -> A -> ... ends in A
    int gemm_blocks = (N_NODES + 127) / 128;
    for (int l = 0; l < N_LAYERS; l++) {
        int sel = (l == 0) ? 2 : (l & 1);
        gemm_fused<<<gemm_blocks, 256, GT_SMEM_BYTES>>>(sel, l, cbrel + (size_t)l * D);
    }

    // pooling
    count_kernel<<<(N_NODES + 255) / 256, 256>>>(batch);
    pool_kernel<<<(N_NODES + POOL_CHUNK - 1) / POOL_CHUNK, D>>>(batch);

    // heads + fusion
    head_kernel<<<1, N_GRAPHS * N_CLASSES>>>(snn_w2, snn_b2, lin_w, lin_b,
                                             fuse_w, fuse_b, out);
}

// round 13
// speedup vs baseline: 1.1380x; 1.1380x over previous
#include <cuda_runtime.h>
#include <cuda_bf16.h>
#include <stdint.h>

#define N_NODES  100000
#define N_EDGES  1600000
#define D        128
#define N_LAYERS 7
#define N_GRAPHS 64
#define N_CLASSES 10
#define SNN_IN   512
#define SNN_H    1024

typedef __nv_bfloat16 bf16;

// ---------------- device scratch (no allocations allowed) ----------------
// Interleaved hi/lo node features: per node 512B = 16 chunk-pairs,
// chunk 2j = hi elems [8j,8j+8), chunk 2j+1 = lo of same elems.
__device__ __align__(16) bf16 g_x [(size_t)N_NODES * 2 * D];
__device__ __align__(16) bf16 g_hA[(size_t)N_NODES * 2 * D];
__device__ __align__(16) bf16 g_hB[(size_t)N_NODES * 2 * D];
__device__ __align__(16) bf16 g_ag[(size_t)N_NODES * 2 * D];

// pre-split weights, [layer][rel/root][n=128][k=128]
__device__ __align__(16) bf16 g_wH[N_LAYERS * 2 * D * D];
__device__ __align__(16) bf16 g_wL[N_LAYERS * 2 * D * D];

__device__ int   g_cnt   [N_NODES];
__device__ int   g_rowptr[N_NODES + 1];
__device__ int   g_cursor[N_NODES];
__device__ int   g_col   [N_EDGES];

__device__ float g_pool[N_GRAPHS * D];
__device__ float g_cnts[N_GRAPHS];
__device__ float g_snnh[N_GRAPHS * SNN_H];

__device__ int   g_is64;

// ---------------- small helpers ----------------
__device__ __forceinline__ uint32_t bf2pack(float a, float b) {
    __nv_bfloat162 t = __float22bfloat162_rn(make_float2(a, b));
    return *(uint32_t*)&t;
}
__device__ __forceinline__ int idx_at(const void* __restrict__ p, long long i, int is64) {
    long long v = is64 ? ((const long long*)p)[i] : (long long)((const int*)p)[i];
    return (int)v;
}
__device__ __forceinline__ int clampi(int v, int lo, int hi) {
    return v < lo ? lo : (v > hi ? hi : v);
}
__device__ __forceinline__ uint32_t smem_u32(const void* p) {
    uint32_t a;
    asm("{ .reg .u64 t; cvta.to.shared.u64 t, %1; cvt.u32.u64 %0, t; }" : "=r"(a) : "l"(p));
    return a;
}
__device__ __forceinline__ void cp16(uint32_t dst, const void* src) {
    asm volatile("cp.async.cg.shared.global [%0], [%1], 16;" :: "r"(dst), "l"(src));
}
#define CP_COMMIT asm volatile("cp.async.commit_group;" ::: "memory")
#define CP_WAIT0  asm volatile("cp.async.wait_group 0;"  ::: "memory")

// ---------------- dtype detection ----------------
__global__ void detect_kernel(const int* __restrict__ ei32) {
    if (threadIdx.x == 0 && blockIdx.x == 0) {
        int orr = 0;
        #pragma unroll 8
        for (int i = 1; i < 256; i += 2) orr |= ei32[i];
        g_is64 = (orr == 0) ? 1 : 0;
    }
}

// ---------------- x -> interleaved hi/lo bf16 ----------------
__global__ void xconv_kernel(const float* __restrict__ x) {
    size_t i = (size_t)blockIdx.x * blockDim.x + threadIdx.x;   // 8 elems/thread
    size_t n8 = (size_t)N_NODES * D / 8;
    if (i >= n8) return;
    float4 v0 = ((const float4*)x)[2 * i];
    float4 v1 = ((const float4*)x)[2 * i + 1];
    uint4 hp, lp;
    hp.x = bf2pack(v0.x, v0.y); hp.y = bf2pack(v0.z, v0.w);
    hp.z = bf2pack(v1.x, v1.y); hp.w = bf2pack(v1.z, v1.w);
    float r0 = v0.x - __bfloat162float(((__nv_bfloat162*)&hp.x)->x);
    float r1 = v0.y - __bfloat162float(((__nv_bfloat162*)&hp.x)->y);
    float r2 = v0.z - __bfloat162float(((__nv_bfloat162*)&hp.y)->x);
    float r3 = v0.w - __bfloat162float(((__nv_bfloat162*)&hp.y)->y);
    float r4 = v1.x - __bfloat162float(((__nv_bfloat162*)&hp.z)->x);
    float r5 = v1.y - __bfloat162float(((__nv_bfloat162*)&hp.z)->y);
    float r6 = v1.z - __bfloat162float(((__nv_bfloat162*)&hp.w)->x);
    float r7 = v1.w - __bfloat162float(((__nv_bfloat162*)&hp.w)->y);
    lp.x = bf2pack(r0, r1); lp.y = bf2pack(r2, r3);
    lp.z = bf2pack(r4, r5); lp.w = bf2pack(r6, r7);
    ((uint4*)g_x)[2 * i]     = hp;
    ((uint4*)g_x)[2 * i + 1] = lp;
}

// ---------------- weight pre-split: [l][s][n][k] ----------------
__global__ void wprep_kernel(const float* __restrict__ cwrel,
                             const float* __restrict__ cwroot) {
    int b = blockIdx.x;                 // l*256 + s*128 + k
    int l = b >> 8, s = (b >> 7) & 1, k = b & 127;
    int n = threadIdx.x;
    const float* w = (s ? cwroot : cwrel) + (size_t)l * D * D;
    float v = w[k * D + n];
    bf16 h = __float2bfloat16(v);
    float r = v - __bfloat162float(h);
    size_t o = ((size_t)(l * 2 + s) * D + n) * D + k;
    g_wH[o] = h;
    g_wL[o] = __float2bfloat16(r);
}

// ---------------- CSR build ----------------
__global__ void zero_kernel() {
    int i = blockIdx.x * blockDim.x + threadIdx.x;
    if (i < N_NODES) g_cnt[i] = 0;
    if (i < N_GRAPHS * D) g_pool[i] = 0.f;
    if (i < N_GRAPHS) g_cnts[i] = 0.f;
}

__global__ void hist_kernel(const void* __restrict__ ei) {
    int e = blockIdx.x * blockDim.x + threadIdx.x;
    if (e >= N_EDGES) return;
    int dst = clampi(idx_at(ei, (long long)N_EDGES + e, g_is64), 0, N_NODES - 1);
    atomicAdd(&g_cnt[dst], 1);
}

// single-block scan, 4 elems/thread, warp-shuffle based
__global__ void scan_kernel() {
    __shared__ int wsum[32];
    __shared__ int s_carry;
    int tid = threadIdx.x, lane = tid & 31, wid = tid >> 5;
    if (tid == 0) { s_carry = 0; g_rowptr[0] = 0; }
    __syncthreads();
    for (int base = 0; base < N_NODES; base += 4096) {
        int i0 = base + tid * 4;
        int v0 = 0, v1 = 0, v2 = 0, v3 = 0;
        if (i0 + 3 < N_NODES) {
            int4 v = *(const int4*)&g_cnt[i0];
            v0 = v.x; v1 = v.y; v2 = v.z; v3 = v.w;
        } else if (i0 < N_NODES) {
            v0 = g_cnt[i0];
            if (i0 + 1 < N_NODES) v1 = g_cnt[i0 + 1];
            if (i0 + 2 < N_NODES) v2 = g_cnt[i0 + 2];
        }
        int s0 = v0, s1 = s0 + v1, s2 = s1 + v2, s3 = s2 + v3;
        int t = s3;
        #pragma unroll
        for (int off = 1; off < 32; off <<= 1) {
            int u = __shfl_up_sync(0xFFFFFFFFu, t, off);
            if (lane >= off) t += u;
        }
        if (lane == 31) wsum[wid] = t;
        __syncthreads();
        if (wid == 0) {
            int w = wsum[lane];
            #pragma unroll
            for (int off = 1; off < 32; off <<= 1) {
                int u = __shfl_up_sync(0xFFFFFFFFu, w, off);
                if (lane >= off) w += u;
            }
            wsum[lane] = w;
        }
        __syncthreads();
        int warpoff = (wid > 0) ? wsum[wid - 1] : 0;
        int throff = s_carry + warpoff + (t - s3);
        if (i0 < N_NODES)     { g_cursor[i0]     = throff;      g_rowptr[i0 + 1] = throff + s0; }
        if (i0 + 1 < N_NODES) { g_cursor[i0 + 1] = throff + s0; g_rowptr[i0 + 2] = throff + s1; }
        if (i0 + 2 < N_NODES) { g_cursor[i0 + 2] = throff + s1; g_rowptr[i0 + 3] = throff + s2; }
        if (i0 + 3 < N_NODES) { g_cursor[i0 + 3] = throff + s2; g_rowptr[i0 + 4] = throff + s3; }
        int tot = wsum[31];
        __syncthreads();
        if (tid == 0) s_carry += tot;
        __syncthreads();
    }
}

__global__ void scatter_kernel(const void* __restrict__ ei) {
    int e = blockIdx.x * blockDim.x + threadIdx.x;
    if (e >= N_EDGES) return;
    int is64 = g_is64;
    int src = clampi(idx_at(ei, e, is64),                      0, N_NODES - 1);
    int dst = clampi(idx_at(ei, (long long)N_EDGES + e, is64), 0, N_NODES - 1);
    int pos = atomicAdd(&g_cursor[dst], 1);
    if (pos >= 0 && pos < N_EDGES) g_col[pos] = src;
}

// ------- aggregation: warp per node, one LDG.128 per lane per neighbor -----
// Lane l reads 16B chunk l of each neighbor (even = hi of 8 elems, odd = lo
// of same 8). Partial sums combined across lane pairs at the end.
__global__ void agg_kernel(int sel) {
    const bf16* __restrict__ curI = (sel == 2) ? g_x : (sel == 1 ? g_hA : g_hB);
    int warp = (blockIdx.x * blockDim.x + threadIdx.x) >> 5;
    int lane = threadIdx.x & 31;
    if (warp >= N_NODES) return;
    int s = g_rowptr[warp];
    int e = g_rowptr[warp + 1];
    float acc[8];
    #pragma unroll
    for (int j = 0; j < 8; j++) acc[j] = 0.f;
    const char* basep = (const char*)curI;
    for (int i = s; i < e; i++) {
        int src = g_col[i];
        uint4 v = *(const uint4*)(basep + (size_t)src * 512 + lane * 16);
        float2 p0 = __bfloat1622float2(*(__nv_bfloat162*)&v.x);
        float2 p1 = __bfloat1622float2(*(__nv_bfloat162*)&v.y);
        float2 p2 = __bfloat1622float2(*(__nv_bfloat162*)&v.z);
        float2 p3 = __bfloat1622float2(*(__nv_bfloat162*)&v.w);
        acc[0] += p0.x; acc[1] += p0.y; acc[2] += p1.x; acc[3] += p1.y;
        acc[4] += p2.x; acc[5] += p2.y; acc[6] += p3.x; acc[7] += p3.y;
    }
    // even lane: add odd lane's (lo) partial sums for the same 8 elems
    float sum[8];
    #pragma unroll
    for (int j = 0; j < 8; j++) {
        float other = __shfl_down_sync(0xFFFFFFFFu, acc[j], 1);
        sum[j] = acc[j] + other;         // valid on even lanes
    }
    // even lane: split to hi/lo packs
    uint32_t hp[4], lp[4];
    #pragma unroll
    for (int j = 0; j < 4; j++) {
        float a = sum[2 * j], b = sum[2 * j + 1];
        hp[j] = bf2pack(a, b);
        lp[j] = bf2pack(a - __bfloat162float(((__nv_bfloat162*)&hp[j])->x),
                        b - __bfloat162float(((__nv_bfloat162*)&hp[j])->y));
    }
    // odd lane fetches even lane's lo pack
    uint32_t lr[4];
    #pragma unroll
    for (int j = 0; j < 4; j++) lr[j] = __shfl_up_sync(0xFFFFFFFFu, lp[j], 1);
    uint4 outv;
    if (lane & 1) outv = make_uint4(lr[0], lr[1], lr[2], lr[3]);
    else          outv = make_uint4(hp[0], hp[1], hp[2], hp[3]);
    *(uint4*)((char*)g_ag + (size_t)warp * 512 + lane * 16) = outv;
}

// ================= mma.sync bf16x3 GraphConv GEMM (R10 config) =============
// CTA: 256 thr / 8 warps, tile M=128 N=128; warp tile 32x64.
// K=256 in 4 chunks of 64; single-stage cp.async staging from interleaved A.

#define APITCH 144              // (64+8) bf16 * 2 bytes, padded row
#define ABUF   18432            // 128 * 144
#define GT_SMEM_BYTES (4 * ABUF)   // Ahi, Alo, Bhi, Blo

__device__ __forceinline__ void mma16816(float* c,
    uint32_t a0, uint32_t a1, uint32_t a2, uint32_t a3,
    uint32_t b0, uint32_t b1)
{
    asm volatile(
        "mma.sync.aligned.m16n8k16.row.col.f32.bf16.bf16.f32 "
        "{%0,%1,%2,%3}, {%4,%5,%6,%7}, {%8,%9}, {%0,%1,%2,%3};"
        : "+f"(c[0]), "+f"(c[1]), "+f"(c[2]), "+f"(c[3])
        : "r"(a0), "r"(a1), "r"(a2), "r"(a3), "r"(b0), "r"(b1));
}

__global__ __launch_bounds__(256) void gemm_tc(int sel, int layer,
                                               const float* __restrict__ brel)
{
    extern __shared__ char sm[];
    char* pAhi = sm;
    char* pAlo = sm + ABUF;
    char* pBhi = sm + 2 * ABUF;
    char* pBlo = sm + 3 * ABUF;
    uint32_t sb32 = smem_u32(sm);

    const bf16* __restrict__ curI = (sel == 2) ? g_x : (sel == 1 ? g_hA : g_hB);
    bf16* __restrict__ outI       = (sel == 1) ? g_hB : g_hA;
    const bf16* __restrict__ wHb = g_wH + (size_t)layer * 2 * D * D;
    const bf16* __restrict__ wLb = g_wL + (size_t)layer * 2 * D * D;

    int tid  = threadIdx.x;
    int lane = tid & 31, wid = tid >> 5;
    int wm = wid & 3, wn = wid >> 2;           // warp grid 4(M) x 2(N)
    int l4 = lane >> 2, l2 = (lane & 3) * 2;
    int m0 = blockIdx.x * 128;

    float acc[2][8][4];
    #pragma unroll
    for (int a = 0; a < 2; a++)
        #pragma unroll
        for (int t = 0; t < 8; t++)
            #pragma unroll
            for (int j = 0; j < 4; j++) acc[a][t][j] = 0.f;

    #pragma unroll 1
    for (int c = 0; c < 4; c++) {
        // ---- stage chunk c: A from interleaved array, B from split weights --
        const char* aB = (const char*)((c < 2) ? g_ag : curI);
        int cb = 8 * (c & 1);                   // first hi-chunk pair index
        const bf16* wH = wHb + (c < 2 ? 0 : D * D);
        const bf16* wL = wLb + (c < 2 ? 0 : D * D);
        int k0 = (c & 1) * 64;

        #pragma unroll
        for (int i = 0; i < 16; i++) {
            const int arr = i >> 2;                 // 0 AH, 1 AL, 2 BH, 3 BL
            int cid = (i & 3) * 256 + tid;          // 0..1023
            int row = cid >> 3, ch = cid & 7;
            uint32_t dst = sb32 + arr * ABUF + row * APITCH + ch * 16;
            if (arr == 0) {
                int m = m0 + row; if (m >= N_NODES) m = 0;
                cp16(dst, aB + (size_t)m * 512 + (cb + ch) * 32);
            } else if (arr == 1) {
                int m = m0 + row; if (m >= N_NODES) m = 0;
                cp16(dst, aB + (size_t)m * 512 + (cb + ch) * 32 + 16);
            } else if (arr == 2) {
                cp16(dst, wH + (size_t)row * D + k0 + ch * 8);
            } else {
                cp16(dst, wL + (size_t)row * D + k0 + ch * 8);
            }
        }
        CP_COMMIT;
        CP_WAIT0;
        __syncthreads();

        // ---- mainloop: 4 k-steps of 16, 3 splits (hh, hl, lh) ----
        #pragma unroll
        for (int ks = 0; ks < 64; ks += 16) {
            uint32_t ah[2][4], al[2][4];
            #pragma unroll
            for (int mt = 0; mt < 2; mt++) {
                int r0 = wm * 32 + mt * 16 + l4;
                int cby = (ks + l2) * 2;
                ah[mt][0] = *(uint32_t*)(pAhi + r0 * APITCH + cby);
                ah[mt][1] = *(uint32_t*)(pAhi + (r0 + 8) * APITCH + cby);
                ah[mt][2] = *(uint32_t*)(pAhi + r0 * APITCH + cby + 16);
                ah[mt][3] = *(uint32_t*)(pAhi + (r0 + 8) * APITCH + cby + 16);
                al[mt][0] = *(uint32_t*)(pAlo + r0 * APITCH + cby);
                al[mt][1] = *(uint32_t*)(pAlo + (r0 + 8) * APITCH + cby);
                al[mt][2] = *(uint32_t*)(pAlo + r0 * APITCH + cby + 16);
                al[mt][3] = *(uint32_t*)(pAlo + (r0 + 8) * APITCH + cby + 16);
            }
            #pragma unroll
            for (int t = 0; t < 8; t++) {
                int n = wn * 64 + t * 8 + l4;
                uint32_t boff = (uint32_t)(n * APITCH + (ks + l2) * 2);
                uint32_t bh0 = *(uint32_t*)(pBhi + boff);
                uint32_t bh1 = *(uint32_t*)(pBhi + boff + 16);
                uint32_t bl0 = *(uint32_t*)(pBlo + boff);
                uint32_t bl1 = *(uint32_t*)(pBlo + boff + 16);
                #pragma unroll
                for (int mt = 0; mt < 2; mt++) {
                    mma16816(acc[mt][t], ah[mt][0], ah[mt][1], ah[mt][2], ah[mt][3], bh0, bh1);
                    mma16816(acc[mt][t], ah[mt][0], ah[mt][1], ah[mt][2], ah[mt][3], bl0, bl1);
                    mma16816(acc[mt][t], al[mt][0], al[mt][1], al[mt][2], al[mt][3], bh0, bh1);
                }
            }
        }
        __syncthreads();
    }

    // ---- epilogue: bias + relu -> interleaved hi/lo out ----
    #pragma unroll
    for (int mt = 0; mt < 2; mt++) {
        int row = m0 + wm * 32 + mt * 16 + l4;
        #pragma unroll
        for (int t = 0; t < 8; t++) {
            int col = wn * 64 + t * 8 + l2;
            float2 bb = *(const float2*)(brel + col);
            uint32_t chunk_off = ((uint32_t)(col >> 3) << 5) + ((col & 7) << 1);
            #pragma unroll
            for (int h = 0; h < 2; h++) {
                int r = row + h * 8;
                if (r < N_NODES) {
                    float ox = fmaxf(acc[mt][t][h * 2 + 0] + bb.x, 0.f);
                    float oy = fmaxf(acc[mt][t][h * 2 + 1] + bb.y, 0.f);
                    uint32_t hp = bf2pack(ox, oy);
                    float rx = ox - __bfloat162float(((__nv_bfloat162*)&hp)->x);
                    float ry = oy - __bfloat162float(((__nv_bfloat162*)&hp)->y);
                    char* op = (char*)outI + (size_t)r * 512 + chunk_off;
                    *(uint32_t*)op        = hp;
                    *(uint32_t*)(op + 16) = bf2pack(rx, ry);
                }
            }
        }
    }
}

// ---------------- pooling (reads final h = g_hA interleaved) ----------------
#define POOL_CHUNK 512
__global__ void pool_kernel(const void* __restrict__ batch) {
    int ch = threadIdx.x;                   // 128
    uint32_t coff = ((uint32_t)(ch >> 3) << 5) + ((ch & 7) << 1);
    int start = blockIdx.x * POOL_CHUNK;
    if (start >= N_NODES) return;
    int end = min(start + POOL_CHUNK, N_NODES);
    int is64 = g_is64;
    int cur = clampi(idx_at(batch, start, is64), 0, N_GRAPHS - 1);
    float acc = 0.f;
    for (int i = start; i < end; i++) {
        int b = clampi(idx_at(batch, i, is64), 0, N_GRAPHS - 1);
        if (b != cur) {
            atomicAdd(&g_pool[cur * D + ch], acc);
            acc = 0.f; cur = b;
        }
        const char* p = (const char*)g_hA + (size_t)i * 512 + coff;
        acc += __bfloat162float(*(const bf16*)p) + __bfloat162float(*(const bf16*)(p + 16));
    }
    atomicAdd(&g_pool[cur * D + ch], acc);
}

__global__ void count_kernel(const void* __restrict__ batch) {
    int i = blockIdx.x * blockDim.x + threadIdx.x;
    if (i >= N_NODES) return;
    int b = clampi(idx_at(batch, i, g_is64), 0, N_GRAPHS - 1);
    atomicAdd(&g_cnts[b], 1.f);
}

// ---------------- SNN layer 1 ----------------
__global__ void snn1_kernel(const float* __restrict__ x, const float* __restrict__ w1,
                            const float* __restrict__ b1) {
    __shared__ float xs[SNN_IN];
    int g = blockIdx.x;
    for (int i = threadIdx.x; i < SNN_IN; i += 256) xs[i] = x[g * SNN_IN + i];
    __syncthreads();
    #pragma unroll
    for (int j = 0; j < 4; j++) {
        int n = threadIdx.x + j * 256;
        float acc = b1[n];
        for (int k = 0; k < SNN_IN; k++)
            acc = fmaf(xs[k], w1[(size_t)k * SNN_H + n], acc);
        g_snnh[g * SNN_H + n] = fmaxf(acc, 0.f);
    }
}

// ---------------- final head + fusion ----------------
__global__ void head_kernel(const float* __restrict__ w2, const float* __restrict__ b2,
                            const float* __restrict__ linw, const float* __restrict__ linb,
                            const float* __restrict__ fw, const float* __restrict__ fb,
                            float* __restrict__ out) {
    __shared__ float s_snn[N_GRAPHS * N_CLASSES];
    __shared__ float s_gnn[N_GRAPHS * N_CLASSES];
    int t = threadIdx.x;                // 640
    int g = t / N_CLASSES, c = t % N_CLASSES;

    float acc = b2[c];
    for (int k = 0; k < SNN_H; k++)
        acc = fmaf(g_snnh[g * SNN_H + k], w2[k * N_CLASSES + c], acc);
    s_snn[g * N_CLASSES + c] = 0.85f * acc;

    float cnt = fmaxf(g_cnts[g], 1.0f);
    float inv = 1.0f / cnt;
    float acc2 = linb[c];
    for (int k = 0; k < D; k++)
        acc2 = fmaf(g_pool[g * D + k] * inv, linw[k * N_CLASSES + c], acc2);
    s_gnn[g * N_CLASSES + c] = acc2;
    __syncthreads();

    float o = fb[c];
    #pragma unroll
    for (int j = 0; j < N_CLASSES; j++) {
        o = fmaf(s_snn[g * N_CLASSES + j], fw[j * N_CLASSES + c], o);
        o = fmaf(s_gnn[g * N_CLASSES + j], fw[(N_CLASSES + j) * N_CLASSES + c], o);
    }
    out[g * N_CLASSES + c] = o;
}

// ---------------- launch ----------------
extern "C" void kernel_launch(void* const* d_in, const int* in_sizes, int n_in,
                              void* d_out, int out_size) {
    const float* snn_x  = (const float*)d_in[0];
    const float* x      = (const float*)d_in[1];
    const void*  ei     = d_in[2];
    const void*  batch  = d_in[3];
    const float* snn_w1 = (const float*)d_in[4];
    const float* snn_b1 = (const float*)d_in[5];
    const float* snn_w2 = (const float*)d_in[6];
    const float* snn_b2 = (const float*)d_in[7];
    const float* cwrel  = (const float*)d_in[8];
    const float* cwroot = (const float*)d_in[9];
    const float* cbrel  = (const float*)d_in[10];
    const float* lin_w  = (const float*)d_in[11];
    const float* lin_b  = (const float*)d_in[12];
    const float* fuse_w = (const float*)d_in[13];
    const float* fuse_b = (const float*)d_in[14];
    float* out = (float*)d_out;

    cudaFuncSetAttribute(gemm_tc, cudaFuncAttributeMaxDynamicSharedMemorySize,
                         GT_SMEM_BYTES);

    // dtype detection + pre-splits + CSR build
    detect_kernel<<<1, 32>>>((const int*)ei);
    xconv_kernel<<<(N_NODES * D / 8 + 255) / 256, 256>>>(x);
    wprep_kernel<<<N_LAYERS * 256, 128>>>(cwrel, cwroot);
    zero_kernel<<<(N_NODES + 255) / 256, 256>>>();
    hist_kernel<<<(N_EDGES + 255) / 256, 256>>>(ei);
    scan_kernel<<<1, 1024>>>();
    scatter_kernel<<<(N_EDGES + 255) / 256, 256>>>(ei);

    // SNN branch (independent)
    snn1_kernel<<<N_GRAPHS, 256>>>(snn_x, snn_w1, snn_b1);

    // 7 GraphConv layers: x -> A -> B -> A -> ... ends in A
    int gemm_blocks = (N_NODES + 127) / 128;
    for (int l = 0; l < N_LAYERS; l++) {
        int sel = (l == 0) ? 2 : (l & 1);
        agg_kernel<<<(N_NODES * 32 + 255) / 256, 256>>>(sel);
        gemm_tc<<<gemm_blocks, 256, GT_SMEM_BYTES>>>(sel, l, cbrel + (size_t)l * D);
    }

    // pooling
    count_kernel<<<(N_NODES + 255) / 256, 256>>>(batch);
    pool_kernel<<<(N_NODES + POOL_CHUNK - 1) / POOL_CHUNK, D>>>(batch);

    // heads + fusion
    head_kernel<<<1, N_GRAPHS * N_CLASSES>>>(snn_w2, snn_b2, lin_w, lin_b,
                                             fuse_w, fuse_b, out);
}

// round 15
// speedup vs baseline: 1.1890x; 1.0448x over previous
#include <cuda_runtime.h>
#include <cuda_bf16.h>
#include <stdint.h>

#define N_NODES  100000
#define N_EDGES  1600000
#define D        128
#define N_LAYERS 7
#define N_GRAPHS 64
#define N_CLASSES 10
#define SNN_IN   512
#define SNN_H    1024

typedef __nv_bfloat16 bf16;

// ---------------- device scratch (no allocations allowed) ----------------
__device__ __align__(16) bf16 g_xH [(size_t)N_NODES * D];
__device__ __align__(16) bf16 g_xL [(size_t)N_NODES * D];
__device__ __align__(16) bf16 g_hAH[(size_t)N_NODES * D];
__device__ __align__(16) bf16 g_hAL[(size_t)N_NODES * D];
__device__ __align__(16) bf16 g_hBH[(size_t)N_NODES * D];
__device__ __align__(16) bf16 g_hBL[(size_t)N_NODES * D];
__device__ __align__(16) bf16 g_agH[(size_t)N_NODES * D];
__device__ __align__(16) bf16 g_agL[(size_t)N_NODES * D];

// pre-split weights, [layer][rel/root][n=128][k=128]
__device__ __align__(16) bf16 g_wH[N_LAYERS * 2 * D * D];
__device__ __align__(16) bf16 g_wL[N_LAYERS * 2 * D * D];

__device__ int   g_cnt   [N_NODES];
__device__ int   g_rowptr[N_NODES + 1];
__device__ int   g_cursor[N_NODES];
__device__ int   g_col   [N_EDGES];

__device__ float g_pool[N_GRAPHS * D];
__device__ float g_cnts[N_GRAPHS];
__device__ float g_snnh[N_GRAPHS * SNN_H];

__device__ int   g_is64;

// ---------------- small helpers ----------------
__device__ __forceinline__ uint32_t bf2pack(float a, float b) {
    __nv_bfloat162 t = __float22bfloat162_rn(make_float2(a, b));
    return *(uint32_t*)&t;
}
__device__ __forceinline__ int idx_at(const void* __restrict__ p, long long i, int is64) {
    long long v = is64 ? ((const long long*)p)[i] : (long long)((const int*)p)[i];
    return (int)v;
}
__device__ __forceinline__ int clampi(int v, int lo, int hi) {
    return v < lo ? lo : (v > hi ? hi : v);
}
__device__ __forceinline__ uint32_t smem_u32(const void* p) {
    uint32_t a;
    asm("{ .reg .u64 t; cvta.to.shared.u64 t, %1; cvt.u32.u64 %0, t; }" : "=r"(a) : "l"(p));
    return a;
}
__device__ __forceinline__ void cp16(uint32_t dst, const void* src) {
    asm volatile("cp.async.cg.shared.global [%0], [%1], 16;" :: "r"(dst), "l"(src));
}
#define CP_COMMIT asm volatile("cp.async.commit_group;" ::: "memory")
#define CP_WAIT0  asm volatile("cp.async.wait_group 0;"  ::: "memory")

__device__ __forceinline__ void ldsm4(uint32_t* r, uint32_t addr) {
    asm volatile("ldmatrix.sync.aligned.m8n8.x4.shared.b16 {%0,%1,%2,%3}, [%4];"
        : "=r"(r[0]), "=r"(r[1]), "=r"(r[2]), "=r"(r[3]) : "r"(addr));
}

// ---------------- dtype detection ----------------
__global__ void detect_kernel(const int* __restrict__ ei32) {
    if (threadIdx.x == 0 && blockIdx.x == 0) {
        int orr = 0;
        #pragma unroll 8
        for (int i = 1; i < 256; i += 2) orr |= ei32[i];
        g_is64 = (orr == 0) ? 1 : 0;
    }
}

// ---------------- x -> hi/lo bf16 ----------------
__global__ void xconv_kernel(const float* __restrict__ x) {
    size_t i = (size_t)blockIdx.x * blockDim.x + threadIdx.x;
    size_t n4 = (size_t)N_NODES * D / 4;
    if (i >= n4) return;
    float4 v = ((const float4*)x)[i];
    uint32_t h01 = bf2pack(v.x, v.y), h23 = bf2pack(v.z, v.w);
    float r0 = v.x - __bfloat162float(((__nv_bfloat162*)&h01)->x);
    float r1 = v.y - __bfloat162float(((__nv_bfloat162*)&h01)->y);
    float r2 = v.z - __bfloat162float(((__nv_bfloat162*)&h23)->x);
    float r3 = v.w - __bfloat162float(((__nv_bfloat162*)&h23)->y);
    ((uint2*)g_xH)[i] = make_uint2(h01, h23);
    ((uint2*)g_xL)[i] = make_uint2(bf2pack(r0, r1), bf2pack(r2, r3));
}

// ---------------- weight pre-split: [l][s][n][k] ----------------
__global__ void wprep_kernel(const float* __restrict__ cwrel,
                             const float* __restrict__ cwroot) {
    int b = blockIdx.x;                 // l*256 + s*128 + k
    int l = b >> 8, s = (b >> 7) & 1, k = b & 127;
    int n = threadIdx.x;
    const float* w = (s ? cwroot : cwrel) + (size_t)l * D * D;
    float v = w[k * D + n];
    bf16 h = __float2bfloat16(v);
    float r = v - __bfloat162float(h);
    size_t o = ((size_t)(l * 2 + s) * D + n) * D + k;
    g_wH[o] = h;
    g_wL[o] = __float2bfloat16(r);
}

// ---------------- CSR build ----------------
__global__ void zero_kernel() {
    int i = blockIdx.x * blockDim.x + threadIdx.x;
    if (i < N_NODES) g_cnt[i] = 0;
    if (i < N_GRAPHS * D) g_pool[i] = 0.f;
    if (i < N_GRAPHS) g_cnts[i] = 0.f;
}

__global__ void hist_kernel(const void* __restrict__ ei) {
    int e = blockIdx.x * blockDim.x + threadIdx.x;
    if (e >= N_EDGES) return;
    int dst = clampi(idx_at(ei, (long long)N_EDGES + e, g_is64), 0, N_NODES - 1);
    atomicAdd(&g_cnt[dst], 1);
}

// single-block scan, 4 elems/thread, warp-shuffle based
__global__ void scan_kernel() {
    __shared__ int wsum[32];
    __shared__ int s_carry;
    int tid = threadIdx.x, lane = tid & 31, wid = tid >> 5;
    if (tid == 0) { s_carry = 0; g_rowptr[0] = 0; }
    __syncthreads();
    for (int base = 0; base < N_NODES; base += 4096) {
        int i0 = base + tid * 4;
        int v0 = 0, v1 = 0, v2 = 0, v3 = 0;
        if (i0 + 3 < N_NODES) {
            int4 v = *(const int4*)&g_cnt[i0];
            v0 = v.x; v1 = v.y; v2 = v.z; v3 = v.w;
        } else if (i0 < N_NODES) {
            v0 = g_cnt[i0];
            if (i0 + 1 < N_NODES) v1 = g_cnt[i0 + 1];
            if (i0 + 2 < N_NODES) v2 = g_cnt[i0 + 2];
        }
        int s0 = v0, s1 = s0 + v1, s2 = s1 + v2, s3 = s2 + v3;
        int t = s3;
        #pragma unroll
        for (int off = 1; off < 32; off <<= 1) {
            int u = __shfl_up_sync(0xFFFFFFFFu, t, off);
            if (lane >= off) t += u;
        }
        if (lane == 31) wsum[wid] = t;
        __syncthreads();
        if (wid == 0) {
            int w = wsum[lane];
            #pragma unroll
            for (int off = 1; off < 32; off <<= 1) {
                int u = __shfl_up_sync(0xFFFFFFFFu, w, off);
                if (lane >= off) w += u;
            }
            wsum[lane] = w;
        }
        __syncthreads();
        int warpoff = (wid > 0) ? wsum[wid - 1] : 0;
        int throff = s_carry + warpoff + (t - s3);
        if (i0 < N_NODES)     { g_cursor[i0]     = throff;      g_rowptr[i0 + 1] = throff + s0; }
        if (i0 + 1 < N_NODES) { g_cursor[i0 + 1] = throff + s0; g_rowptr[i0 + 2] = throff + s1; }
        if (i0 + 2 < N_NODES) { g_cursor[i0 + 2] = throff + s1; g_rowptr[i0 + 3] = throff + s2; }
        if (i0 + 3 < N_NODES) { g_cursor[i0 + 3] = throff + s2; g_rowptr[i0 + 4] = throff + s3; }
        int tot = wsum[31];
        __syncthreads();
        if (tid == 0) s_carry += tot;
        __syncthreads();
    }
}

__global__ void scatter_kernel(const void* __restrict__ ei) {
    int e = blockIdx.x * blockDim.x + threadIdx.x;
    if (e >= N_EDGES) return;
    int is64 = g_is64;
    int src = clampi(idx_at(ei, e, is64),                      0, N_NODES - 1);
    int dst = clampi(idx_at(ei, (long long)N_EDGES + e, is64), 0, N_NODES - 1);
    int pos = atomicAdd(&g_cursor[dst], 1);
    if (pos >= 0 && pos < N_EDGES) g_col[pos] = src;
}

// ---------------- aggregation: warp per node, hi/lo in, hi/lo out ----------
__global__ void agg_kernel(int sel) {
    const bf16* __restrict__ H = (sel == 2) ? g_xH : (sel == 1 ? g_hAH : g_hBH);
    const bf16* __restrict__ L = (sel == 2) ? g_xL : (sel == 1 ? g_hAL : g_hBL);
    int warp = (blockIdx.x * blockDim.x + threadIdx.x) >> 5;
    int lane = threadIdx.x & 31;
    if (warp >= N_NODES) return;
    int s = g_rowptr[warp];
    int e = g_rowptr[warp + 1];
    float4 acc = make_float4(0.f, 0.f, 0.f, 0.f);
    for (int i = s; i < e; i++) {
        int src = g_col[i];
        uint2 hv = *(const uint2*)(H + (size_t)src * D + lane * 4);
        uint2 lv = *(const uint2*)(L + (size_t)src * D + lane * 4);
        float2 a0 = __bfloat1622float2(*(__nv_bfloat162*)&hv.x);
        float2 a1 = __bfloat1622float2(*(__nv_bfloat162*)&hv.y);
        float2 b0 = __bfloat1622float2(*(__nv_bfloat162*)&lv.x);
        float2 b1 = __bfloat1622float2(*(__nv_bfloat162*)&lv.y);
        acc.x += a0.x + b0.x; acc.y += a0.y + b0.y;
        acc.z += a1.x + b1.x; acc.w += a1.y + b1.y;
    }
    uint32_t h01 = bf2pack(acc.x, acc.y), h23 = bf2pack(acc.z, acc.w);
    float r0 = acc.x - __bfloat162float(((__nv_bfloat162*)&h01)->x);
    float r1 = acc.y - __bfloat162float(((__nv_bfloat162*)&h01)->y);
    float r2 = acc.z - __bfloat162float(((__nv_bfloat162*)&h23)->x);
    float r3 = acc.w - __bfloat162float(((__nv_bfloat162*)&h23)->y);
    size_t o = (size_t)warp * D + lane * 4;
    *(uint2*)(g_agH + o) = make_uint2(h01, h23);
    *(uint2*)(g_agL + o) = make_uint2(bf2pack(r0, r1), bf2pack(r2, r3));
}

// ================= mma.sync bf16x3 GraphConv GEMM (R10 + ldmatrix) =========
// CTA: 256 thr / 8 warps, tile M=128 N=128; warp tile 32x64.
// K=256 in 4 chunks of 64; staging via cp.async; fragments via ldmatrix.x4.

#define APITCH 144              // (64+8) bf16 * 2 bytes, padded row
#define ABUF   18432            // 128 * 144
#define GT_SMEM_BYTES (4 * ABUF)   // Ahi, Alo, Bhi, Blo

__device__ __forceinline__ void mma16816(float* c,
    uint32_t a0, uint32_t a1, uint32_t a2, uint32_t a3,
    uint32_t b0, uint32_t b1)
{
    asm volatile(
        "mma.sync.aligned.m16n8k16.row.col.f32.bf16.bf16.f32 "
        "{%0,%1,%2,%3}, {%4,%5,%6,%7}, {%8,%9}, {%0,%1,%2,%3};"
        : "+f"(c[0]), "+f"(c[1]), "+f"(c[2]), "+f"(c[3])
        : "r"(a0), "r"(a1), "r"(a2), "r"(a3), "r"(b0), "r"(b1));
}

__global__ __launch_bounds__(256) void gemm_tc(int sel, int layer,
                                               const float* __restrict__ brel)
{
    extern __shared__ char sm[];
    uint32_t sb32 = smem_u32(sm);

    const bf16* __restrict__ curH = (sel == 2) ? g_xH : (sel == 1 ? g_hAH : g_hBH);
    const bf16* __restrict__ curL = (sel == 2) ? g_xL : (sel == 1 ? g_hAL : g_hBL);
    bf16* __restrict__ outH = (sel == 1) ? g_hBH : g_hAH;
    bf16* __restrict__ outL = (sel == 1) ? g_hBL : g_hAL;
    const bf16* __restrict__ wHb = g_wH + (size_t)layer * 2 * D * D;
    const bf16* __restrict__ wLb = g_wL + (size_t)layer * 2 * D * D;

    int tid  = threadIdx.x;
    int lane = tid & 31, wid = tid >> 5;
    int wm = wid & 3, wn = wid >> 2;           // warp grid 4(M) x 2(N)
    int l4 = lane >> 2, l2 = (lane & 3) * 2;
    int m0 = blockIdx.x * 128;

    // ldmatrix per-lane invariant address components (bytes)
    uint32_t aRowOff = (uint32_t)(wm * 32 + (lane & 15)) * APITCH;
    uint32_t aKoffB  = ((lane >> 4) & 1) * 16;            // 8 elems = 16B
    uint32_t bRowOff = (uint32_t)(wn * 64 + (lane & 7) + ((lane >> 4) & 1) * 8) * APITCH;
    uint32_t bKoffB  = ((lane >> 3) & 1) * 16;

    float acc[2][8][4];
    #pragma unroll
    for (int a = 0; a < 2; a++)
        #pragma unroll
        for (int t = 0; t < 8; t++)
            #pragma unroll
            for (int j = 0; j < 4; j++) acc[a][t][j] = 0.f;

    #pragma unroll 1
    for (int c = 0; c < 4; c++) {
        // ---- stage chunk c: 4096 x 16B cp.async, 16 per thread ----
        const bf16* aH = (c < 2) ? g_agH : curH;
        const bf16* aL = (c < 2) ? g_agL : curL;
        int acoff = (c & 1) * 64;
        const bf16* wH = wHb + (c < 2 ? 0 : D * D);
        const bf16* wL = wLb + (c < 2 ? 0 : D * D);
        int k0 = (c & 1) * 64;

        #pragma unroll
        for (int i = 0; i < 16; i++) {
            const int arr = i >> 2;                 // 0 AH, 1 AL, 2 BH, 3 BL
            int cid = (i & 3) * 256 + tid;          // 0..1023
            int row = cid >> 3, ch = cid & 7;
            uint32_t dst = sb32 + arr * ABUF + row * APITCH + ch * 16;
            if (arr == 0) {
                int m = m0 + row; if (m >= N_NODES) m = 0;
                cp16(dst, aH + (size_t)m * D + acoff + ch * 8);
            } else if (arr == 1) {
                int m = m0 + row; if (m >= N_NODES) m = 0;
                cp16(dst, aL + (size_t)m * D + acoff + ch * 8);
            } else if (arr == 2) {
                cp16(dst, wH + (size_t)row * D + k0 + ch * 8);
            } else {
                cp16(dst, wL + (size_t)row * D + k0 + ch * 8);
            }
        }
        CP_COMMIT;
        CP_WAIT0;
        __syncthreads();

        // ---- mainloop: 4 k-steps of 16, 3 splits (hh, hl, lh) ----
        #pragma unroll
        for (int ks = 0; ks < 64; ks += 16) {
            uint32_t ah[2][4], al[2][4];
            uint32_t aBase = sb32 + aRowOff + (uint32_t)ks * 2 + aKoffB;
            ldsm4(ah[0], aBase);
            ldsm4(ah[1], aBase + 16 * APITCH);
            ldsm4(al[0], aBase + ABUF);
            ldsm4(al[1], aBase + ABUF + 16 * APITCH);

            #pragma unroll
            for (int tp = 0; tp < 4; tp++) {
                uint32_t bh[4], bl[4];
                uint32_t bAddr = sb32 + 2 * ABUF + bRowOff
                               + (uint32_t)(16 * tp) * APITCH
                               + (uint32_t)ks * 2 + bKoffB;
                ldsm4(bh, bAddr);
                ldsm4(bl, bAddr + ABUF);
                #pragma unroll
                for (int tt = 0; tt < 2; tt++) {
                    int t = tp * 2 + tt;
                    uint32_t bh0 = bh[tt * 2], bh1 = bh[tt * 2 + 1];
                    uint32_t bl0 = bl[tt * 2], bl1 = bl[tt * 2 + 1];
                    #pragma unroll
                    for (int mt = 0; mt < 2; mt++) {
                        mma16816(acc[mt][t], ah[mt][0], ah[mt][1], ah[mt][2], ah[mt][3], bh0, bh1);
                        mma16816(acc[mt][t], ah[mt][0], ah[mt][1], ah[mt][2], ah[mt][3], bl0, bl1);
                        mma16816(acc[mt][t], al[mt][0], al[mt][1], al[mt][2], al[mt][3], bh0, bh1);
                    }
                }
            }
        }
        __syncthreads();
    }

    // ---- epilogue: bias + relu -> hi/lo bf16 out ----
    #pragma unroll
    for (int mt = 0; mt < 2; mt++) {
        int row = m0 + wm * 32 + mt * 16 + l4;
        #pragma unroll
        for (int t = 0; t < 8; t++) {
            int col = wn * 64 + t * 8 + l2;
            float2 bb = *(const float2*)(brel + col);
            #pragma unroll
            for (int h = 0; h < 2; h++) {
                int r = row + h * 8;
                if (r < N_NODES) {
                    float ox = fmaxf(acc[mt][t][h * 2 + 0] + bb.x, 0.f);
                    float oy = fmaxf(acc[mt][t][h * 2 + 1] + bb.y, 0.f);
                    uint32_t hp = bf2pack(ox, oy);
                    float rx = ox - __bfloat162float(((__nv_bfloat162*)&hp)->x);
                    float ry = oy - __bfloat162float(((__nv_bfloat162*)&hp)->y);
                    size_t o = (size_t)r * D + col;
                    *(uint32_t*)(outH + o) = hp;
                    *(uint32_t*)(outL + o) = bf2pack(rx, ry);
                }
            }
        }
    }
}

// ---------------- pooling (reads final h = bufA hi/lo) ----------------
#define POOL_CHUNK 512
__global__ void pool_kernel(const void* __restrict__ batch) {
    int ch = threadIdx.x;                   // 128
    int start = blockIdx.x * POOL_CHUNK;
    if (start >= N_NODES) return;
    int end = min(start + POOL_CHUNK, N_NODES);
    int is64 = g_is64;
    int cur = clampi(idx_at(batch, start, is64), 0, N_GRAPHS - 1);
    float acc = 0.f;
    for (int i = start; i < end; i++) {
        int b = clampi(idx_at(batch, i, is64), 0, N_GRAPHS - 1);
        if (b != cur) {
            atomicAdd(&g_pool[cur * D + ch], acc);
            acc = 0.f; cur = b;
        }
        size_t o = (size_t)i * D + ch;
        acc += __bfloat162float(g_hAH[o]) + __bfloat162float(g_hAL[o]);
    }
    atomicAdd(&g_pool[cur * D + ch], acc);
}

__global__ void count_kernel(const void* __restrict__ batch) {
    int i = blockIdx.x * blockDim.x + threadIdx.x;
    if (i >= N_NODES) return;
    int b = clampi(idx_at(batch, i, g_is64), 0, N_GRAPHS - 1);
    atomicAdd(&g_cnts[b], 1.f);
}

// ---------------- SNN layer 1 ----------------
__global__ void snn1_kernel(const float* __restrict__ x, const float* __restrict__ w1,
                            const float* __restrict__ b1) {
    __shared__ float xs[SNN_IN];
    int g = blockIdx.x;
    for (int i = threadIdx.x; i < SNN_IN; i += 256) xs[i] = x[g * SNN_IN + i];
    __syncthreads();
    #pragma unroll
    for (int j = 0; j < 4; j++) {
        int n = threadIdx.x + j * 256;
        float acc = b1[n];
        for (int k = 0; k < SNN_IN; k++)
            acc = fmaf(xs[k], w1[(size_t)k * SNN_H + n], acc);
        g_snnh[g * SNN_H + n] = fmaxf(acc, 0.f);
    }
}

// ---------------- final head + fusion ----------------
__global__ void head_kernel(const float* __restrict__ w2, const float* __restrict__ b2,
                            const float* __restrict__ linw, const float* __restrict__ linb,
                            const float* __restrict__ fw, const float* __restrict__ fb,
                            float* __restrict__ out) {
    __shared__ float s_snn[N_GRAPHS * N_CLASSES];
    __shared__ float s_gnn[N_GRAPHS * N_CLASSES];
    int t = threadIdx.x;                // 640
    int g = t / N_CLASSES, c = t % N_CLASSES;

    float acc = b2[c];
    for (int k = 0; k < SNN_H; k++)
        acc = fmaf(g_snnh[g * SNN_H + k], w2[k * N_CLASSES + c], acc);
    s_snn[g * N_CLASSES + c] = 0.85f * acc;

    float cnt = fmaxf(g_cnts[g], 1.0f);
    float inv = 1.0f / cnt;
    float acc2 = linb[c];
    for (int k = 0; k < D; k++)
        acc2 = fmaf(g_pool[g * D + k] * inv, linw[k * N_CLASSES + c], acc2);
    s_gnn[g * N_CLASSES + c] = acc2;
    __syncthreads();

    float o = fb[c];
    #pragma unroll
    for (int j = 0; j < N_CLASSES; j++) {
        o = fmaf(s_snn[g * N_CLASSES + j], fw[j * N_CLASSES + c], o);
        o = fmaf(s_gnn[g * N_CLASSES + j], fw[(N_CLASSES + j) * N_CLASSES + c], o);
    }
    out[g * N_CLASSES + c] = o;
}

// ---------------- launch ----------------
extern "C" void kernel_launch(void* const* d_in, const int* in_sizes, int n_in,
                              void* d_out, int out_size) {
    const float* snn_x  = (const float*)d_in[0];
    const float* x      = (const float*)d_in[1];
    const void*  ei     = d_in[2];
    const void*  batch  = d_in[3];
    const float* snn_w1 = (const float*)d_in[4];
    const float* snn_b1 = (const float*)d_in[5];
    const float* snn_w2 = (const float*)d_in[6];
    const float* snn_b2 = (const float*)d_in[7];
    const float* cwrel  = (const float*)d_in[8];
    const float* cwroot = (const float*)d_in[9];
    const float* cbrel  = (const float*)d_in[10];
    const float* lin_w  = (const float*)d_in[11];
    const float* lin_b  = (const float*)d_in[12];
    const float* fuse_w = (const float*)d_in[13];
    const float* fuse_b = (const float*)d_in[14];
    float* out = (float*)d_out;

    cudaFuncSetAttribute(gemm_tc, cudaFuncAttributeMaxDynamicSharedMemorySize,
                         GT_SMEM_BYTES);

    // dtype detection + pre-splits + CSR build
    detect_kernel<<<1, 32>>>((const int*)ei);
    xconv_kernel<<<(N_NODES * D / 4 + 255) / 256, 256>>>(x);
    wprep_kernel<<<N_LAYERS * 256, 128>>>(cwrel, cwroot);
    zero_kernel<<<(N_NODES + 255) / 256, 256>>>();
    hist_kernel<<<(N_EDGES + 255) / 256, 256>>>(ei);
    scan_kernel<<<1, 1024>>>();
    scatter_kernel<<<(N_EDGES + 255) / 256, 256>>>(ei);

    // SNN branch (independent)
    snn1_kernel<<<N_GRAPHS, 256>>>(snn_x, snn_w1, snn_b1);

    // 7 GraphConv layers: x -> A -> B -> A -> ... ends in A
    int gemm_blocks = (N_NODES + 127) / 128;
    for (int l = 0; l < N_LAYERS; l++) {
        int sel = (l == 0) ? 2 : (l & 1);
        agg_kernel<<<(N_NODES * 32 + 255) / 256, 256>>>(sel);
        gemm_tc<<<gemm_blocks, 256, GT_SMEM_BYTES>>>(sel, l, cbrel + (size_t)l * D);
    }

    // pooling
    count_kernel<<<(N_NODES + 255) / 256, 256>>>(batch);
    pool_kernel<<<(N_NODES + POOL_CHUNK - 1) / POOL_CHUNK, D>>>(batch);

    // heads + fusion
    head_kernel<<<1, N_GRAPHS * N_CLASSES>>>(snn_w2, snn_b2, lin_w, lin_b,
                                             fuse_w, fuse_b, out);
}

// round 17
// speedup vs baseline: 1.4582x; 1.2264x over previous
#include <cuda_runtime.h>
#include <cuda_bf16.h>
#include <stdint.h>

#define N_NODES  100000
#define N_EDGES  1600000
#define D        128
#define N_LAYERS 7
#define N_GRAPHS 64
#define N_CLASSES 10
#define SNN_IN   512
#define SNN_H    1024

typedef __nv_bfloat16 bf16;

// ---------------- device scratch (no allocations allowed) ----------------
__device__ __align__(16) bf16 g_xH [(size_t)N_NODES * D];
__device__ __align__(16) bf16 g_xL [(size_t)N_NODES * D];
__device__ __align__(16) bf16 g_hAH[(size_t)N_NODES * D];
__device__ __align__(16) bf16 g_hAL[(size_t)N_NODES * D];
__device__ __align__(16) bf16 g_hBH[(size_t)N_NODES * D];
__device__ __align__(16) bf16 g_hBL[(size_t)N_NODES * D];
__device__ __align__(16) bf16 g_agH[(size_t)N_NODES * D];
__device__ __align__(16) bf16 g_agL[(size_t)N_NODES * D];

// pre-split weights, [layer][rel/root][n=128][k=128]
__device__ __align__(16) bf16 g_wH[N_LAYERS * 2 * D * D];
__device__ __align__(16) bf16 g_wL[N_LAYERS * 2 * D * D];

__device__ int   g_cnt   [N_NODES];
__device__ int   g_rowptr[N_NODES + 1];
__device__ int   g_cursor[N_NODES];
__device__ int   g_col   [N_EDGES];

__device__ float g_pool[N_GRAPHS * D];
__device__ float g_cnts[N_GRAPHS];
__device__ float g_snnh[N_GRAPHS * SNN_H];

__device__ int   g_is64;

// ---------------- small helpers ----------------
__device__ __forceinline__ uint32_t bf2pack(float a, float b) {
    __nv_bfloat162 t = __float22bfloat162_rn(make_float2(a, b));
    return *(uint32_t*)&t;
}
__device__ __forceinline__ int idx_at(const void* __restrict__ p, long long i, int is64) {
    long long v = is64 ? ((const long long*)p)[i] : (long long)((const int*)p)[i];
    return (int)v;
}
__device__ __forceinline__ int clampi(int v, int lo, int hi) {
    return v < lo ? lo : (v > hi ? hi : v);
}
__device__ __forceinline__ uint32_t smem_u32(const void* p) {
    uint32_t a;
    asm("{ .reg .u64 t; cvta.to.shared.u64 t, %1; cvt.u32.u64 %0, t; }" : "=r"(a) : "l"(p));
    return a;
}
__device__ __forceinline__ void cp16(uint32_t dst, const void* src) {
    asm volatile("cp.async.cg.shared.global [%0], [%1], 16;" :: "r"(dst), "l"(src));
}
#define CP_COMMIT asm volatile("cp.async.commit_group;" ::: "memory")
#define CP_WAIT0  asm volatile("cp.async.wait_group 0;"  ::: "memory")

// ---------------- dtype detection ----------------
__global__ void detect_kernel(const int* __restrict__ ei32) {
    if (threadIdx.x == 0 && blockIdx.x == 0) {
        int orr = 0;
        #pragma unroll 8
        for (int i = 1; i < 256; i += 2) orr |= ei32[i];
        g_is64 = (orr == 0) ? 1 : 0;
    }
}

// ---------------- x -> hi/lo bf16 ----------------
__global__ void xconv_kernel(const float* __restrict__ x) {
    size_t i = (size_t)blockIdx.x * blockDim.x + threadIdx.x;
    size_t n4 = (size_t)N_NODES * D / 4;
    if (i >= n4) return;
    float4 v = ((const float4*)x)[i];
    uint32_t h01 = bf2pack(v.x, v.y), h23 = bf2pack(v.z, v.w);
    float r0 = v.x - __bfloat162float(((__nv_bfloat162*)&h01)->x);
    float r1 = v.y - __bfloat162float(((__nv_bfloat162*)&h01)->y);
    float r2 = v.z - __bfloat162float(((__nv_bfloat162*)&h23)->x);
    float r3 = v.w - __bfloat162float(((__nv_bfloat162*)&h23)->y);
    ((uint2*)g_xH)[i] = make_uint2(h01, h23);
    ((uint2*)g_xL)[i] = make_uint2(bf2pack(r0, r1), bf2pack(r2, r3));
}

// ---------------- weight pre-split: [l][s][n][k] ----------------
__global__ void wprep_kernel(const float* __restrict__ cwrel,
                             const float* __restrict__ cwroot) {
    int b = blockIdx.x;                 // l*256 + s*128 + k
    int l = b >> 8, s = (b >> 7) & 1, k = b & 127;
    int n = threadIdx.x;
    const float* w = (s ? cwroot : cwrel) + (size_t)l * D * D;
    float v = w[k * D + n];
    bf16 h = __float2bfloat16(v);
    float r = v - __bfloat162float(h);
    size_t o = ((size_t)(l * 2 + s) * D + n) * D + k;
    g_wH[o] = h;
    g_wL[o] = __float2bfloat16(r);
}

// ---------------- CSR build ----------------
__global__ void zero_kernel() {
    int i = blockIdx.x * blockDim.x + threadIdx.x;
    if (i < N_NODES) g_cnt[i] = 0;
    if (i < N_GRAPHS * D) g_pool[i] = 0.f;
    if (i < N_GRAPHS) g_cnts[i] = 0.f;
}

__global__ void hist_kernel(const void* __restrict__ ei) {
    int e = blockIdx.x * blockDim.x + threadIdx.x;
    if (e >= N_EDGES) return;
    int dst = clampi(idx_at(ei, (long long)N_EDGES + e, g_is64), 0, N_NODES - 1);
    atomicAdd(&g_cnt[dst], 1);
}

// single-block scan, 4 elems/thread, warp-shuffle based
__global__ void scan_kernel() {
    __shared__ int wsum[32];
    __shared__ int s_carry;
    int tid = threadIdx.x, lane = tid & 31, wid = tid >> 5;
    if (tid == 0) { s_carry = 0; g_rowptr[0] = 0; }
    __syncthreads();
    for (int base = 0; base < N_NODES; base += 4096) {
        int i0 = base + tid * 4;
        int v0 = 0, v1 = 0, v2 = 0, v3 = 0;
        if (i0 + 3 < N_NODES) {
            int4 v = *(const int4*)&g_cnt[i0];
            v0 = v.x; v1 = v.y; v2 = v.z; v3 = v.w;
        } else if (i0 < N_NODES) {
            v0 = g_cnt[i0];
            if (i0 + 1 < N_NODES) v1 = g_cnt[i0 + 1];
            if (i0 + 2 < N_NODES) v2 = g_cnt[i0 + 2];
        }
        int s0 = v0, s1 = s0 + v1, s2 = s1 + v2, s3 = s2 + v3;
        int t = s3;
        #pragma unroll
        for (int off = 1; off < 32; off <<= 1) {
            int u = __shfl_up_sync(0xFFFFFFFFu, t, off);
            if (lane >= off) t += u;
        }
        if (lane == 31) wsum[wid] = t;
        __syncthreads();
        if (wid == 0) {
            int w = wsum[lane];
            #pragma unroll
            for (int off = 1; off < 32; off <<= 1) {
                int u = __shfl_up_sync(0xFFFFFFFFu, w, off);
                if (lane >= off) w += u;
            }
            wsum[lane] = w;
        }
        __syncthreads();
        int warpoff = (wid > 0) ? wsum[wid - 1] : 0;
        int throff = s_carry + warpoff + (t - s3);
        if (i0 < N_NODES)     { g_cursor[i0]     = throff;      g_rowptr[i0 + 1] = throff + s0; }
        if (i0 + 1 < N_NODES) { g_cursor[i0 + 1] = throff + s0; g_rowptr[i0 + 2] = throff + s1; }
        if (i0 + 2 < N_NODES) { g_cursor[i0 + 2] = throff + s1; g_rowptr[i0 + 3] = throff + s2; }
        if (i0 + 3 < N_NODES) { g_cursor[i0 + 3] = throff + s2; g_rowptr[i0 + 4] = throff + s3; }
        int tot = wsum[31];
        __syncthreads();
        if (tid == 0) s_carry += tot;
        __syncthreads();
    }
}

__global__ void scatter_kernel(const void* __restrict__ ei) {
    int e = blockIdx.x * blockDim.x + threadIdx.x;
    if (e >= N_EDGES) return;
    int is64 = g_is64;
    int src = clampi(idx_at(ei, e, is64),                      0, N_NODES - 1);
    int dst = clampi(idx_at(ei, (long long)N_EDGES + e, is64), 0, N_NODES - 1);
    int pos = atomicAdd(&g_cursor[dst], 1);
    if (pos >= 0 && pos < N_EDGES) g_col[pos] = src;
}

// ------ aggregation: warp per node, hi-only gather (lo is noise-level) -----
__global__ void agg_kernel(int sel) {
    const bf16* __restrict__ H = (sel == 2) ? g_xH : (sel == 1 ? g_hAH : g_hBH);
    int warp = (blockIdx.x * blockDim.x + threadIdx.x) >> 5;
    int lane = threadIdx.x & 31;
    if (warp >= N_NODES) return;
    int s = g_rowptr[warp];
    int e = g_rowptr[warp + 1];
    float4 acc = make_float4(0.f, 0.f, 0.f, 0.f);
    for (int i = s; i < e; i++) {
        int src = g_col[i];
        uint2 hv = *(const uint2*)(H + (size_t)src * D + lane * 4);
        float2 a0 = __bfloat1622float2(*(__nv_bfloat162*)&hv.x);
        float2 a1 = __bfloat1622float2(*(__nv_bfloat162*)&hv.y);
        acc.x += a0.x; acc.y += a0.y;
        acc.z += a1.x; acc.w += a1.y;
    }
    uint32_t h01 = bf2pack(acc.x, acc.y), h23 = bf2pack(acc.z, acc.w);
    float r0 = acc.x - __bfloat162float(((__nv_bfloat162*)&h01)->x);
    float r1 = acc.y - __bfloat162float(((__nv_bfloat162*)&h01)->y);
    float r2 = acc.z - __bfloat162float(((__nv_bfloat162*)&h23)->x);
    float r3 = acc.w - __bfloat162float(((__nv_bfloat162*)&h23)->y);
    size_t o = (size_t)warp * D + lane * 4;
    *(uint2*)(g_agH + o) = make_uint2(h01, h23);
    *(uint2*)(g_agL + o) = make_uint2(bf2pack(r0, r1), bf2pack(r2, r3));
}

// ================= mma.sync bf16x3 GraphConv GEMM (R10 config) =============
// CTA: 256 thr / 8 warps, tile M=128 N=128; warp tile 32x64.
// K=256 in 4 chunks of 64; staging via cp.async; scalar LDS fragments.

#define APITCH 144              // (64+8) bf16 * 2 bytes, padded row
#define ABUF   18432            // 128 * 144
#define GT_SMEM_BYTES (4 * ABUF)   // Ahi, Alo, Bhi, Blo

__device__ __forceinline__ void mma16816(float* c,
    uint32_t a0, uint32_t a1, uint32_t a2, uint32_t a3,
    uint32_t b0, uint32_t b1)
{
    asm volatile(
        "mma.sync.aligned.m16n8k16.row.col.f32.bf16.bf16.f32 "
        "{%0,%1,%2,%3}, {%4,%5,%6,%7}, {%8,%9}, {%0,%1,%2,%3};"
        : "+f"(c[0]), "+f"(c[1]), "+f"(c[2]), "+f"(c[3])
        : "r"(a0), "r"(a1), "r"(a2), "r"(a3), "r"(b0), "r"(b1));
}

__global__ __launch_bounds__(256) void gemm_tc(int sel, int layer,
                                               const float* __restrict__ brel)
{
    extern __shared__ char sm[];
    char* pAhi = sm;
    char* pAlo = sm + ABUF;
    char* pBhi = sm + 2 * ABUF;
    char* pBlo = sm + 3 * ABUF;
    uint32_t sb32 = smem_u32(sm);

    const bf16* __restrict__ curH = (sel == 2) ? g_xH : (sel == 1 ? g_hAH : g_hBH);
    const bf16* __restrict__ curL = (sel == 2) ? g_xL : (sel == 1 ? g_hAL : g_hBL);
    bf16* __restrict__ outH = (sel == 1) ? g_hBH : g_hAH;
    bf16* __restrict__ outL = (sel == 1) ? g_hBL : g_hAL;
    const bf16* __restrict__ wHb = g_wH + (size_t)layer * 2 * D * D;
    const bf16* __restrict__ wLb = g_wL + (size_t)layer * 2 * D * D;

    int tid  = threadIdx.x;
    int lane = tid & 31, wid = tid >> 5;
    int wm = wid & 3, wn = wid >> 2;           // warp grid 4(M) x 2(N)
    int l4 = lane >> 2, l2 = (lane & 3) * 2;
    int m0 = blockIdx.x * 128;

    float acc[2][8][4];
    #pragma unroll
    for (int a = 0; a < 2; a++)
        #pragma unroll
        for (int t = 0; t < 8; t++)
            #pragma unroll
            for (int j = 0; j < 4; j++) acc[a][t][j] = 0.f;

    #pragma unroll 1
    for (int c = 0; c < 4; c++) {
        // ---- stage chunk c: 4096 x 16B cp.async, 16 per thread ----
        const bf16* aH = (c < 2) ? g_agH : curH;
        const bf16* aL = (c < 2) ? g_agL : curL;
        int acoff = (c & 1) * 64;
        const bf16* wH = wHb + (c < 2 ? 0 : D * D);
        const bf16* wL = wLb + (c < 2 ? 0 : D * D);
        int k0 = (c & 1) * 64;

        #pragma unroll
        for (int i = 0; i < 16; i++) {
            const int arr = i >> 2;                 // 0 AH, 1 AL, 2 BH, 3 BL
            int cid = (i & 3) * 256 + tid;          // 0..1023
            int row = cid >> 3, ch = cid & 7;
            uint32_t dst = sb32 + arr * ABUF + row * APITCH + ch * 16;
            if (arr == 0) {
                int m = m0 + row; if (m >= N_NODES) m = 0;
                cp16(dst, aH + (size_t)m * D + acoff + ch * 8);
            } else if (arr == 1) {
                int m = m0 + row; if (m >= N_NODES) m = 0;
                cp16(dst, aL + (size_t)m * D + acoff + ch * 8);
            } else if (arr == 2) {
                cp16(dst, wH + (size_t)row * D + k0 + ch * 8);
            } else {
                cp16(dst, wL + (size_t)row * D + k0 + ch * 8);
            }
        }
        CP_COMMIT;
        CP_WAIT0;
        __syncthreads();

        // ---- mainloop: 4 k-steps of 16, 3 splits (hh, hl, lh) ----
        #pragma unroll
        for (int ks = 0; ks < 64; ks += 16) {
            uint32_t ah[2][4], al[2][4];
            #pragma unroll
            for (int mt = 0; mt < 2; mt++) {
                int r0 = wm * 32 + mt * 16 + l4;
                int cby = (ks + l2) * 2;
                ah[mt][0] = *(uint32_t*)(pAhi + r0 * APITCH + cby);
                ah[mt][1] = *(uint32_t*)(pAhi + (r0 + 8) * APITCH + cby);
                ah[mt][2] = *(uint32_t*)(pAhi + r0 * APITCH + cby + 16);
                ah[mt][3] = *(uint32_t*)(pAhi + (r0 + 8) * APITCH + cby + 16);
                al[mt][0] = *(uint32_t*)(pAlo + r0 * APITCH + cby);
                al[mt][1] = *(uint32_t*)(pAlo + (r0 + 8) * APITCH + cby);
                al[mt][2] = *(uint32_t*)(pAlo + r0 * APITCH + cby + 16);
                al[mt][3] = *(uint32_t*)(pAlo + (r0 + 8) * APITCH + cby + 16);
            }
            #pragma unroll
            for (int t = 0; t < 8; t++) {
                int n = wn * 64 + t * 8 + l4;
                uint32_t boff = (uint32_t)(n * APITCH + (ks + l2) * 2);
                uint32_t bh0 = *(uint32_t*)(pBhi + boff);
                uint32_t bh1 = *(uint32_t*)(pBhi + boff + 16);
                uint32_t bl0 = *(uint32_t*)(pBlo + boff);
                uint32_t bl1 = *(uint32_t*)(pBlo + boff + 16);
                #pragma unroll
                for (int mt = 0; mt < 2; mt++) {
                    mma16816(acc[mt][t], ah[mt][0], ah[mt][1], ah[mt][2], ah[mt][3], bh0, bh1);
                    mma16816(acc[mt][t], ah[mt][0], ah[mt][1], ah[mt][2], ah[mt][3], bl0, bl1);
                    mma16816(acc[mt][t], al[mt][0], al[mt][1], al[mt][2], al[mt][3], bh0, bh1);
                }
            }
        }
        __syncthreads();
    }

    // ---- epilogue: bias + relu -> hi/lo bf16 out ----
    #pragma unroll
    for (int mt = 0; mt < 2; mt++) {
        int row = m0 + wm * 32 + mt * 16 + l4;
        #pragma unroll
        for (int t = 0; t < 8; t++) {
            int col = wn * 64 + t * 8 + l2;
            float2 bb = *(const float2*)(brel + col);
            #pragma unroll
            for (int h = 0; h < 2; h++) {
                int r = row + h * 8;
                if (r < N_NODES) {
                    float ox = fmaxf(acc[mt][t][h * 2 + 0] + bb.x, 0.f);
                    float oy = fmaxf(acc[mt][t][h * 2 + 1] + bb.y, 0.f);
                    uint32_t hp = bf2pack(ox, oy);
                    float rx = ox - __bfloat162float(((__nv_bfloat162*)&hp)->x);
                    float ry = oy - __bfloat162float(((__nv_bfloat162*)&hp)->y);
                    size_t o = (size_t)r * D + col;
                    *(uint32_t*)(outH + o) = hp;
                    *(uint32_t*)(outL + o) = bf2pack(rx, ry);
                }
            }
        }
    }
}

// ---------------- pooling (reads final h = bufA hi/lo) ----------------
#define POOL_CHUNK 512
__global__ void pool_kernel(const void* __restrict__ batch) {
    int ch = threadIdx.x;                   // 128
    int start = blockIdx.x * POOL_CHUNK;
    if (start >= N_NODES) return;
    int end = min(start + POOL_CHUNK, N_NODES);
    int is64 = g_is64;
    int cur = clampi(idx_at(batch, start, is64), 0, N_GRAPHS - 1);
    float acc = 0.f;
    for (int i = start; i < end; i++) {
        int b = clampi(idx_at(batch, i, is64), 0, N_GRAPHS - 1);
        if (b != cur) {
            atomicAdd(&g_pool[cur * D + ch], acc);
            acc = 0.f; cur = b;
        }
        size_t o = (size_t)i * D + ch;
        acc += __bfloat162float(g_hAH[o]) + __bfloat162float(g_hAL[o]);
    }
    atomicAdd(&g_pool[cur * D + ch], acc);
}

__global__ void count_kernel(const void* __restrict__ batch) {
    int i = blockIdx.x * blockDim.x + threadIdx.x;
    if (i >= N_NODES) return;
    int b = clampi(idx_at(batch, i, g_is64), 0, N_GRAPHS - 1);
    atomicAdd(&g_cnts[b], 1.f);
}

// ---------------- SNN layer 1 ----------------
__global__ void snn1_kernel(const float* __restrict__ x, const float* __restrict__ w1,
                            const float* __restrict__ b1) {
    __shared__ float xs[SNN_IN];
    int g = blockIdx.x;
    for (int i = threadIdx.x; i < SNN_IN; i += 256) xs[i] = x[g * SNN_IN + i];
    __syncthreads();
    #pragma unroll
    for (int j = 0; j < 4; j++) {
        int n = threadIdx.x + j * 256;
        float acc = b1[n];
        for (int k = 0; k < SNN_IN; k++)
            acc = fmaf(xs[k], w1[(size_t)k * SNN_H + n], acc);
        g_snnh[g * SNN_H + n] = fmaxf(acc, 0.f);
    }
}

// ---------------- final head + fusion ----------------
__global__ void head_kernel(const float* __restrict__ w2, const float* __restrict__ b2,
                            const float* __restrict__ linw, const float* __restrict__ linb,
                            const float* __restrict__ fw, const float* __restrict__ fb,
                            float* __restrict__ out) {
    __shared__ float s_snn[N_GRAPHS * N_CLASSES];
    __shared__ float s_gnn[N_GRAPHS * N_CLASSES];
    int t = threadIdx.x;                // 640
    int g = t / N_CLASSES, c = t % N_CLASSES;

    float acc = b2[c];
    for (int k = 0; k < SNN_H; k++)
        acc = fmaf(g_snnh[g * SNN_H + k], w2[k * N_CLASSES + c], acc);
    s_snn[g * N_CLASSES + c] = 0.85f * acc;

    float cnt = fmaxf(g_cnts[g], 1.0f);
    float inv = 1.0f / cnt;
    float acc2 = linb[c];
    for (int k = 0; k < D; k++)
        acc2 = fmaf(g_pool[g * D + k] * inv, linw[k * N_CLASSES + c], acc2);
    s_gnn[g * N_CLASSES + c] = acc2;
    __syncthreads();

    float o = fb[c];
    #pragma unroll
    for (int j = 0; j < N_CLASSES; j++) {
        o = fmaf(s_snn[g * N_CLASSES + j], fw[j * N_CLASSES + c], o);
        o = fmaf(s_gnn[g * N_CLASSES + j], fw[(N_CLASSES + j) * N_CLASSES + c], o);
    }
    out[g * N_CLASSES + c] = o;
}

// ---------------- launch ----------------
extern "C" void kernel_launch(void* const* d_in, const int* in_sizes, int n_in,
                              void* d_out, int out_size) {
    const float* snn_x  = (const float*)d_in[0];
    const float* x      = (const float*)d_in[1];
    const void*  ei     = d_in[2];
    const void*  batch  = d_in[3];
    const float* snn_w1 = (const float*)d_in[4];
    const float* snn_b1 = (const float*)d_in[5];
    const float* snn_w2 = (const float*)d_in[6];
    const float* snn_b2 = (const float*)d_in[7];
    const float* cwrel  = (const float*)d_in[8];
    const float* cwroot = (const float*)d_in[9];
    const float* cbrel  = (const float*)d_in[10];
    const float* lin_w  = (const float*)d_in[11];
    const float* lin_b  = (const float*)d_in[12];
    const float* fuse_w = (const float*)d_in[13];
    const float* fuse_b = (const float*)d_in[14];
    float* out = (float*)d_out;

    cudaFuncSetAttribute(gemm_tc, cudaFuncAttributeMaxDynamicSharedMemorySize,
                         GT_SMEM_BYTES);

    // dtype detection + pre-splits + CSR build
    detect_kernel<<<1, 32>>>((const int*)ei);
    xconv_kernel<<<(N_NODES * D / 4 + 255) / 256, 256>>>(x);
    wprep_kernel<<<N_LAYERS * 256, 128>>>(cwrel, cwroot);
    zero_kernel<<<(N_NODES + 255) / 256, 256>>>();
    hist_kernel<<<(N_EDGES + 255) / 256, 256>>>(ei);
    scan_kernel<<<1, 1024>>>();
    scatter_kernel<<<(N_EDGES + 255) / 256, 256>>>(ei);

    // SNN branch (independent)
    snn1_kernel<<<N_GRAPHS, 256>>>(snn_x, snn_w1, snn_b1);

    // 7 GraphConv layers: x -> A -> B -> A -> ... ends in A
    int gemm_blocks = (N_NODES + 127) / 128;
    for (int l = 0; l < N_LAYERS; l++) {
        int sel = (l == 0) ? 2 : (l & 1);
        agg_kernel<<<(N_NODES * 32 + 255) / 256, 256>>>(sel);
        gemm_tc<<<gemm_blocks, 256, GT_SMEM_BYTES>>>(sel, l, cbrel + (size_t)l * D);
    }

    // pooling
    count_kernel<<<(N_NODES + 255) / 256, 256>>>(batch);
    pool_kernel<<<(N_NODES + POOL_CHUNK - 1) / POOL_CHUNK, D>>>(batch);

    // heads + fusion
    head_kernel<<<1, N_GRAPHS * N_CLASSES>>>(snn_w2, snn_b2, lin_w, lin_b,
                                             fuse_w, fuse_b, out);
}